// round 10
// baseline (speedup 1.0000x reference)
#include <cuda_runtime.h>
#include <math.h>

#define NN 100000
#define NE 1600000
#define NG 512
#define NF 64
#define H1 128
#define H2 64
#define SCB 98            // scan blocks: ceil(NN/1024)
#define TPB 64            // nodes per block in dense kernels

// ---------------- device scratch ----------------
__device__ float g_h1[NN * H1];      // h after nfc; later reused for z2 (64-d)
__device__ float g_s1[NN * H1];      // z1 = W1 h
__device__ float g_h2[NN * H2];      // final normalized conv2 output
__device__ float g_e[NN];
__device__ int   g_cnt[NN];
__device__ int   g_off[NN + 1];
__device__ int   g_cur[NN];
__device__ int   g_csr[NE];
__device__ int   g_gs[NG + 1];
__device__ int   g_sagg[SCB];
__device__ int   g_sflag[SCB];

__device__ __forceinline__ float gelu_f(float x) {
    return 0.5f * x * (1.0f + erff(x * 0.70710678118654752f));
}
__device__ __forceinline__ float sigmoid_f(float x) {
    return 1.0f / (1.0f + expf(-x));
}

// ---------------- init ----------------
__global__ void __launch_bounds__(256) k_zero() {
    int i = blockIdx.x * blockDim.x + threadIdx.x;
    int T = gridDim.x * blockDim.x;
    for (int j = i; j < NN; j += T) { g_cnt[j] = 0; g_cur[j] = 0; }
    if (i < SCB) { g_sflag[i] = 0; g_sagg[i] = 0; }
    if (i == 0) g_off[NN] = NE;
}

// ---------------- nfc (64 nodes/block) + edge counting fold ----------------
__global__ void __launch_bounds__(256) k_nfc(const float* __restrict__ x,
                                             const float* __restrict__ W,
                                             const float* __restrict__ b,
                                             const int* __restrict__ ei) {
    extern __shared__ float sm[];
    float* wt = sm;                  // [64][128] transposed (32 KB)
    float* xs = sm + NF * H1;        // [64][64]  (16 KB)
    int tid = threadIdx.x;

    // edge counting: this block's slice of 1024 edges
    {
        int eb = blockIdx.x * 1024 + tid * 4;
#pragma unroll
        for (int i = 0; i < 4; i++)
            if (eb + i < NE) atomicAdd(&g_cnt[ei[NE + eb + i]], 1);
    }

    for (int i = tid; i < H1 * NF; i += 256) {
        int o = i >> 6, k = i & 63;
        wt[k * H1 + o] = W[i];
    }
    int warp = tid >> 5, lane = tid & 31;
    int nb = blockIdx.x * TPB;
#pragma unroll
    for (int t = 0; t < 8; t++) {
        int row = warp * 8 + t;
        int n = nb + row;
        if (n < NN) {
            float2 xv = *(const float2*)&x[n * NF + lane * 2];
            *(float2*)&xs[row * NF + lane * 2] = xv;
        }
    }
    __syncthreads();
    float4 bias = *(const float4*)&b[lane * 4];
    float4 acc[8];
#pragma unroll
    for (int t = 0; t < 8; t++) acc[t] = bias;
    const float* rp = &xs[warp * 8 * NF];
#pragma unroll 4
    for (int k = 0; k < NF; k++) {
        float4 w = *(const float4*)&wt[k * H1 + lane * 4];
#pragma unroll
        for (int t = 0; t < 8; t++) {
            float v = rp[t * NF + k];
            acc[t].x = fmaf(v, w.x, acc[t].x);
            acc[t].y = fmaf(v, w.y, acc[t].y);
            acc[t].z = fmaf(v, w.z, acc[t].z);
            acc[t].w = fmaf(v, w.w, acc[t].w);
        }
    }
#pragma unroll
    for (int t = 0; t < 8; t++) {
        int n = nb + warp * 8 + t;
        if (n < NN) {
            float4 a = acc[t];
            a.x = gelu_f(a.x); a.y = gelu_f(a.y);
            a.z = gelu_f(a.z); a.w = gelu_f(a.w);
            *(float4*)&g_h1[n * H1 + lane * 4] = a;
        }
    }
}

// ---------------- single-pass scan (decoupled lookback) + gstart fold ----------------
__global__ void __launch_bounds__(256) k_scan(const int* __restrict__ batch) {
    __shared__ int sm[256];
    __shared__ int addsh;
    int tid = threadIdx.x;
    int b = blockIdx.x;
    if (tid == 0) addsh = 0;
    int idx = b * 1024 + tid * 4;
    int v0 = 0, v1 = 0, v2 = 0, v3 = 0;
    if (idx     < NN) v0 = g_cnt[idx];
    if (idx + 1 < NN) v1 = g_cnt[idx + 1];
    if (idx + 2 < NN) v2 = g_cnt[idx + 2];
    if (idx + 3 < NN) v3 = g_cnt[idx + 3];
    int t = v0 + v1 + v2 + v3;
    sm[tid] = t;
    __syncthreads();
    for (int off = 1; off < 256; off <<= 1) {
        int u = (tid >= off) ? sm[tid - off] : 0;
        __syncthreads();
        sm[tid] += u;
        __syncthreads();
    }
    if (tid == 0) {
        g_sagg[b] = sm[255];
        __threadfence();
        atomicExch(&g_sflag[b], 1);
    }
    int excl = sm[tid] - t;
    int myadd = 0;
    for (int i = tid; i < b; i += 256) {
        while (((volatile int*)g_sflag)[i] == 0) { }
        myadd += ((volatile int*)g_sagg)[i];
    }
#pragma unroll
    for (int off = 16; off; off >>= 1) myadd += __shfl_xor_sync(0xFFFFFFFFu, myadd, off);
    if ((tid & 31) == 0 && myadd) atomicAdd(&addsh, myadd);
    __syncthreads();
    int add = addsh;
    if (idx     < NN) g_off[idx]     = excl + add;
    if (idx + 1 < NN) g_off[idx + 1] = excl + add + v0;
    if (idx + 2 < NN) g_off[idx + 2] = excl + add + v0 + v1;
    if (idx + 3 < NN) g_off[idx + 3] = excl + add + v0 + v1 + v2;
#pragma unroll
    for (int i = 0; i < 4; i++) {
        int n = idx + i;
        if (n < NN) {
            int bb = batch[n];
            int bp = (n == 0) ? -1 : batch[n - 1];
            for (int g = bp + 1; g <= bb; g++) g_gs[g] = n;
            if (n == NN - 1)
                for (int g = bb + 1; g <= NG; g++) g_gs[g] = NN;
        }
    }
}

__global__ void __launch_bounds__(256) k_scatter(const int* __restrict__ ei) {
    int e = blockIdx.x * blockDim.x + threadIdx.x;
    if (e < NE) {
        int s = ei[e];
        int d = ei[NE + e];
        int pos = atomicAdd(&g_cur[d], 1);
        g_csr[g_off[d] + pos] = s;
    }
}

// ---------------- gemm1t: g_s1 = g_h1 @ W1.T (no bias, no act) ----------------
__global__ void __launch_bounds__(256) k_gemm1t(const float* __restrict__ W) {
    extern __shared__ float sm[];
    float* wt = sm;                  // [128][128] transposed (64 KB)
    float* as = sm + H1 * H1;        // [64][128] (32 KB)
    int tid = threadIdx.x;
    for (int i = tid; i < H1 * H1; i += 256) {
        int o = i >> 7, k = i & 127;
        wt[k * H1 + o] = W[i];
    }
    int nb = blockIdx.x * TPB;
    for (int i = tid; i < TPB * H1 / 4; i += 256) {
        int row = (i * 4) >> 7;
        int k   = (i * 4) & 127;
        int n = nb + row;
        float4 v = (n < NN) ? *(const float4*)&g_h1[n * H1 + k]
                            : make_float4(0.f, 0.f, 0.f, 0.f);
        *(float4*)&as[row * H1 + k] = v;
    }
    __syncthreads();
    int warp = tid >> 5, lane = tid & 31;
    float4 acc[8];
#pragma unroll
    for (int t = 0; t < 8; t++) acc[t] = make_float4(0.f, 0.f, 0.f, 0.f);
    const float* rp = &as[warp * 8 * H1];
#pragma unroll 4
    for (int k = 0; k < H1; k++) {
        float4 w = *(const float4*)&wt[k * H1 + lane * 4];
#pragma unroll
        for (int t = 0; t < 8; t++) {
            float v = rp[t * H1 + k];
            acc[t].x = fmaf(v, w.x, acc[t].x);
            acc[t].y = fmaf(v, w.y, acc[t].y);
            acc[t].z = fmaf(v, w.z, acc[t].z);
            acc[t].w = fmaf(v, w.w, acc[t].w);
        }
    }
#pragma unroll
    for (int t = 0; t < 8; t++) {
        int n = nb + warp * 8 + t;
        if (n < NN)
            *(float4*)&g_s1[n * H1 + lane * 4] = acc[t];
    }
}

// ---------------- gather1: agg z1, +b1, gelu -> s; fused z2 = W2 s -> g_h1(64-d) ----------------
__global__ void __launch_bounds__(256) k_gather1(const float* __restrict__ W2,
                                                 const float* __restrict__ b1) {
    extern __shared__ float sm[];
    float* w2t = sm;                 // [128][64] transposed (32 KB)
    float* ssh = sm + H1 * H2;       // [8 warps][128] (4 KB)
    int tid = threadIdx.x;
    for (int i = tid; i < H2 * H1; i += 256) {
        int o = i >> 7, k = i & 127;
        w2t[k * H2 + o] = W2[i];
    }
    __syncthreads();
    int warp = tid >> 5, lane = tid & 31;
    int n = blockIdx.x * 8 + warp;
    if (n >= NN) return;
    const float* src = g_s1;
    float4 a = *(const float4*)&src[n * H1 + lane * 4];   // self z1
    int e0 = g_off[n], e1 = g_off[n + 1];
    int j = e0;
    for (; j + 7 < e1; j += 8) {
        int s0 = g_csr[j],     s1 = g_csr[j + 1], s2 = g_csr[j + 2], s3 = g_csr[j + 3];
        int s4 = g_csr[j + 4], s5 = g_csr[j + 5], s6 = g_csr[j + 6], s7 = g_csr[j + 7];
        float4 v0 = *(const float4*)&src[s0 * H1 + lane * 4];
        float4 v1 = *(const float4*)&src[s1 * H1 + lane * 4];
        float4 v2 = *(const float4*)&src[s2 * H1 + lane * 4];
        float4 v3 = *(const float4*)&src[s3 * H1 + lane * 4];
        float4 v4 = *(const float4*)&src[s4 * H1 + lane * 4];
        float4 v5 = *(const float4*)&src[s5 * H1 + lane * 4];
        float4 v6 = *(const float4*)&src[s6 * H1 + lane * 4];
        float4 v7 = *(const float4*)&src[s7 * H1 + lane * 4];
        a.x += ((v0.x + v1.x) + (v2.x + v3.x)) + ((v4.x + v5.x) + (v6.x + v7.x));
        a.y += ((v0.y + v1.y) + (v2.y + v3.y)) + ((v4.y + v5.y) + (v6.y + v7.y));
        a.z += ((v0.z + v1.z) + (v2.z + v3.z)) + ((v4.z + v5.z) + (v6.z + v7.z));
        a.w += ((v0.w + v1.w) + (v2.w + v3.w)) + ((v4.w + v5.w) + (v6.w + v7.w));
    }
    if (j + 3 < e1) {
        int s0 = g_csr[j], s1 = g_csr[j + 1], s2 = g_csr[j + 2], s3 = g_csr[j + 3];
        float4 v0 = *(const float4*)&src[s0 * H1 + lane * 4];
        float4 v1 = *(const float4*)&src[s1 * H1 + lane * 4];
        float4 v2 = *(const float4*)&src[s2 * H1 + lane * 4];
        float4 v3 = *(const float4*)&src[s3 * H1 + lane * 4];
        a.x += (v0.x + v1.x) + (v2.x + v3.x);
        a.y += (v0.y + v1.y) + (v2.y + v3.y);
        a.z += (v0.z + v1.z) + (v2.z + v3.z);
        a.w += (v0.w + v1.w) + (v2.w + v3.w);
        j += 4;
    }
    for (; j < e1; j++) {
        int s0 = g_csr[j];
        float4 v0 = *(const float4*)&src[s0 * H1 + lane * 4];
        a.x += v0.x; a.y += v0.y; a.z += v0.z; a.w += v0.w;
    }
    // s = gelu(agg + b1)
    float4 bb = *(const float4*)&b1[lane * 4];
    a.x = gelu_f(a.x + bb.x); a.y = gelu_f(a.y + bb.y);
    a.z = gelu_f(a.z + bb.z); a.w = gelu_f(a.w + bb.w);
    // stage s into smem for the warp-local matvec
    float* sw = &ssh[warp * H1];
    *(float4*)&sw[lane * 4] = a;
    __syncwarp();
    // z2 = W2 s  (each lane: 2 outputs)
    float2 acc = make_float2(0.f, 0.f);
#pragma unroll 8
    for (int k = 0; k < H1; k++) {
        float v = sw[k];
        float2 w = *(const float2*)&w2t[k * H2 + lane * 2];
        acc.x = fmaf(v, w.x, acc.x);
        acc.y = fmaf(v, w.y, acc.y);
    }
    *(float2*)&g_h1[n * H2 + lane * 2] = acc;   // z2 packed 64-d into g_h1
}

// ---------------- gather2 (64-d): agg z2, +b2, gelu, normalize -> g_h2 ----------------
__global__ void __launch_bounds__(256) k_gather2(const float* __restrict__ b2,
                                                 float* __restrict__ out_h) {
    int n = (blockIdx.x * 256 + threadIdx.x) >> 5;
    int lane = threadIdx.x & 31;
    if (n >= NN) return;
    const float* src = g_h1;   // z2, 64-d
    float2 a = *(const float2*)&src[n * H2 + lane * 2];
    int e0 = g_off[n], e1 = g_off[n + 1];
    int j = e0;
    for (; j + 7 < e1; j += 8) {
        int s0 = g_csr[j],     s1 = g_csr[j + 1], s2 = g_csr[j + 2], s3 = g_csr[j + 3];
        int s4 = g_csr[j + 4], s5 = g_csr[j + 5], s6 = g_csr[j + 6], s7 = g_csr[j + 7];
        float2 v0 = *(const float2*)&src[s0 * H2 + lane * 2];
        float2 v1 = *(const float2*)&src[s1 * H2 + lane * 2];
        float2 v2 = *(const float2*)&src[s2 * H2 + lane * 2];
        float2 v3 = *(const float2*)&src[s3 * H2 + lane * 2];
        float2 v4 = *(const float2*)&src[s4 * H2 + lane * 2];
        float2 v5 = *(const float2*)&src[s5 * H2 + lane * 2];
        float2 v6 = *(const float2*)&src[s6 * H2 + lane * 2];
        float2 v7 = *(const float2*)&src[s7 * H2 + lane * 2];
        a.x += ((v0.x + v1.x) + (v2.x + v3.x)) + ((v4.x + v5.x) + (v6.x + v7.x));
        a.y += ((v0.y + v1.y) + (v2.y + v3.y)) + ((v4.y + v5.y) + (v6.y + v7.y));
    }
    if (j + 3 < e1) {
        int s0 = g_csr[j], s1 = g_csr[j + 1], s2 = g_csr[j + 2], s3 = g_csr[j + 3];
        float2 v0 = *(const float2*)&src[s0 * H2 + lane * 2];
        float2 v1 = *(const float2*)&src[s1 * H2 + lane * 2];
        float2 v2 = *(const float2*)&src[s2 * H2 + lane * 2];
        float2 v3 = *(const float2*)&src[s3 * H2 + lane * 2];
        a.x += (v0.x + v1.x) + (v2.x + v3.x);
        a.y += (v0.y + v1.y) + (v2.y + v3.y);
        j += 4;
    }
    for (; j < e1; j++) {
        int s0 = g_csr[j];
        float2 v0 = *(const float2*)&src[s0 * H2 + lane * 2];
        a.x += v0.x; a.y += v0.y;
    }
    float2 bb = *(const float2*)&b2[lane * 2];
    a.x = gelu_f(a.x + bb.x);
    a.y = gelu_f(a.y + bb.y);
    float ssq = a.x * a.x + a.y * a.y;
#pragma unroll
    for (int off = 16; off; off >>= 1) ssq += __shfl_xor_sync(0xFFFFFFFFu, ssq, off);
    float inv = 1.0f / fmaxf(sqrtf(ssq), 1e-12f);
    a.x *= inv; a.y *= inv;
    *(float2*)&g_h2[n * H2 + lane * 2] = a;
    if (out_h) *(float2*)&out_h[n * H2 + lane * 2] = a;
}

// ---------------- fused Set2Set (4 steps) + final MLP: one block per graph ----------------
__global__ void __launch_bounds__(256) k_s2s(
        const float* __restrict__ Wih0, const float* __restrict__ Whh0,
        const float* __restrict__ bih0, const float* __restrict__ bhh0,
        const float* __restrict__ Wih1, const float* __restrict__ Whh1,
        const float* __restrict__ bih1, const float* __restrict__ bhh1,
        const float* __restrict__ fc1W, const float* __restrict__ fc1b,
        const float* __restrict__ fc2W, const float* __restrict__ fc2b,
        float* __restrict__ z) {
    __shared__ float h0[H2], c0[H2], h1[H2], c1[H2], qs[2 * H2];
    __shared__ float gb[4 * H2], red[8], rbuf[8 * H2];
    __shared__ float smax, ssum;
    int g = blockIdx.x;
    int tid = threadIdx.x, warp = tid >> 5, lane = tid & 31;
    int gs = g_gs[g], ge = g_gs[g + 1];
    if (tid < H2) { h0[tid] = 0.0f; c0[tid] = 0.0f; h1[tid] = 0.0f; c1[tid] = 0.0f; }
    if (tid < 2 * H2) qs[tid] = 0.0f;
    __syncthreads();

    for (int step = 0; step < 4; step++) {
        for (int r = warp; r < 4 * H2; r += 8) {
            const float* wi = &Wih0[r * 2 * H2];
            float p = wi[lane] * qs[lane] + wi[lane + 32] * qs[lane + 32]
                    + wi[lane + 64] * qs[lane + 64] + wi[lane + 96] * qs[lane + 96];
            const float* wh = &Whh0[r * H2];
            p += wh[lane] * h0[lane] + wh[lane + 32] * h0[lane + 32];
#pragma unroll
            for (int off = 16; off; off >>= 1) p += __shfl_xor_sync(0xFFFFFFFFu, p, off);
            if (lane == 0) gb[r] = p + bih0[r] + bhh0[r];
        }
        __syncthreads();
        if (tid < H2) {
            float i = sigmoid_f(gb[tid]);
            float f = sigmoid_f(gb[H2 + tid]);
            float gg = tanhf(gb[2 * H2 + tid]);
            float o = sigmoid_f(gb[3 * H2 + tid]);
            float c = f * c0[tid] + i * gg;
            c0[tid] = c;
            h0[tid] = o * tanhf(c);
        }
        __syncthreads();
        for (int r = warp; r < 4 * H2; r += 8) {
            const float* wi = &Wih1[r * H2];
            float p = wi[lane] * h0[lane] + wi[lane + 32] * h0[lane + 32];
            const float* wh = &Whh1[r * H2];
            p += wh[lane] * h1[lane] + wh[lane + 32] * h1[lane + 32];
#pragma unroll
            for (int off = 16; off; off >>= 1) p += __shfl_xor_sync(0xFFFFFFFFu, p, off);
            if (lane == 0) gb[r] = p + bih1[r] + bhh1[r];
        }
        __syncthreads();
        if (tid < H2) {
            float i = sigmoid_f(gb[tid]);
            float f = sigmoid_f(gb[H2 + tid]);
            float gg = tanhf(gb[2 * H2 + tid]);
            float o = sigmoid_f(gb[3 * H2 + tid]);
            float c = f * c1[tid] + i * gg;
            c1[tid] = c;
            float h = o * tanhf(c);
            h1[tid] = h;
            qs[tid] = h;
        }
        __syncthreads();
        float wmax = -3.4e38f;
        for (int n = gs + warp; n < ge; n += 8) {
            float2 hv = *(const float2*)&g_h2[n * H2 + lane * 2];
            float e = hv.x * qs[lane * 2] + hv.y * qs[lane * 2 + 1];
#pragma unroll
            for (int off = 16; off; off >>= 1) e += __shfl_xor_sync(0xFFFFFFFFu, e, off);
            if (lane == 0) g_e[n] = e;
            wmax = fmaxf(wmax, e);
        }
        if (lane == 0) red[warp] = wmax;
        __syncthreads();
        if (tid == 0) {
            float m = red[0];
            for (int w = 1; w < 8; w++) m = fmaxf(m, red[w]);
            smax = m;
        }
        __syncthreads();
        float m = smax;
        float ps = 0.0f;
        for (int n = gs + tid; n < ge; n += 256) {
            float ex = expf(g_e[n] - m);
            g_e[n] = ex;
            ps += ex;
        }
#pragma unroll
        for (int off = 16; off; off >>= 1) ps += __shfl_xor_sync(0xFFFFFFFFu, ps, off);
        if (lane == 0) red[warp] = ps;
        __syncthreads();
        if (tid == 0) {
            float s = 0.0f;
            for (int w = 0; w < 8; w++) s += red[w];
            ssum = s;
        }
        __syncthreads();
        float inv = 1.0f / (ssum + 1e-16f);
        float rx = 0.0f, ry = 0.0f;
        for (int n = gs + warp; n < ge; n += 8) {
            float a = g_e[n] * inv;
            float2 hv = *(const float2*)&g_h2[n * H2 + lane * 2];
            rx = fmaf(a, hv.x, rx);
            ry = fmaf(a, hv.y, ry);
        }
        rbuf[warp * H2 + lane * 2]     = rx;
        rbuf[warp * H2 + lane * 2 + 1] = ry;
        __syncthreads();
        if (tid < H2) {
            float r = 0.0f;
            for (int w = 0; w < 8; w++) r += rbuf[w * H2 + tid];
            qs[H2 + tid] = r;
        }
        __syncthreads();
    }

    for (int r = warp; r < 32; r += 8) {
        const float* wr = &fc1W[r * 2 * H2];
        float p = wr[lane] * qs[lane] + wr[lane + 32] * qs[lane + 32]
                + wr[lane + 64] * qs[lane + 64] + wr[lane + 96] * qs[lane + 96];
#pragma unroll
        for (int off = 16; off; off >>= 1) p += __shfl_xor_sync(0xFFFFFFFFu, p, off);
        if (lane == 0) gb[r] = gelu_f(p + fc1b[r]);
    }
    __syncthreads();
    if (warp == 0) {
        float v = gb[lane] * fc2W[lane];
#pragma unroll
        for (int off = 16; off; off >>= 1) v += __shfl_xor_sync(0xFFFFFFFFu, v, off);
        if (lane == 0) z[g] = v + fc2b[0];
    }
}

// ---------------- host ----------------
extern "C" void kernel_launch(void* const* d_in, const int* in_sizes, int n_in,
                              void* d_out, int out_size) {
    const float* x     = (const float*)d_in[0];
    const int*   ei    = (const int*)d_in[1];
    const int*   batch = (const int*)d_in[2];
    const float* nfcW  = (const float*)d_in[3];
    const float* nfcb  = (const float*)d_in[4];
    const float* gc1W  = (const float*)d_in[5];
    const float* gc1b  = (const float*)d_in[6];
    const float* gc2W  = (const float*)d_in[7];
    const float* gc2b  = (const float*)d_in[8];
    const float* l0Wih = (const float*)d_in[9];
    const float* l0Whh = (const float*)d_in[10];
    const float* l0bih = (const float*)d_in[11];
    const float* l0bhh = (const float*)d_in[12];
    const float* l1Wih = (const float*)d_in[13];
    const float* l1Whh = (const float*)d_in[14];
    const float* l1bih = (const float*)d_in[15];
    const float* l1bhh = (const float*)d_in[16];
    const float* fc1W  = (const float*)d_in[17];
    const float* fc1b  = (const float*)d_in[18];
    const float* fc2W  = (const float*)d_in[19];
    const float* fc2b  = (const float*)d_in[20];

    float* out = (float*)d_out;
    float* out_h = (out_size >= NG + NN * H2) ? (out + NG) : nullptr;

    int nblk = (NN + TPB - 1) / TPB;                      // 1563
    int g1blk = (NN + 7) / 8;                             // 8 warps/block: 12500
    int g2blk = (NN * 32 + 255) / 256;                    // 12500
    size_t sm_nfc   = (size_t)(NF * H1 + TPB * NF) * 4;   // 48 KB
    size_t sm_gemm1 = (size_t)(H1 * H1 + TPB * H1) * 4;   // 96 KB
    size_t sm_gath1 = (size_t)(H1 * H2 + 8 * H1) * 4;     // 36 KB
    cudaFuncSetAttribute(k_nfc,    cudaFuncAttributeMaxDynamicSharedMemorySize, (int)sm_nfc);
    cudaFuncSetAttribute(k_gemm1t, cudaFuncAttributeMaxDynamicSharedMemorySize, (int)sm_gemm1);

    k_zero<<<128, 256>>>();
    k_nfc<<<nblk, 256, sm_nfc>>>(x, nfcW, nfcb, ei);
    k_scan<<<SCB, 256>>>(batch);
    k_scatter<<<(NE + 255) / 256, 256>>>(ei);
    k_gemm1t<<<nblk, 256, sm_gemm1>>>(gc1W);
    k_gather1<<<g1blk, 256, sm_gath1>>>(gc2W, gc1b);
    k_gather2<<<g2blk, 256>>>(gc2b, out_h);
    k_s2s<<<NG, 256>>>(l0Wih, l0Whh, l0bih, l0bhh,
                       l1Wih, l1Whh, l1bih, l1bhh,
                       fc1W, fc1b, fc2W, fc2b, out);
}

// round 11
// speedup vs baseline: 1.2896x; 1.2896x over previous
#include <cuda_runtime.h>
#include <math.h>

#define NN 100000
#define NE 1600000
#define NG 512
#define NF 64
#define H1 128
#define H2 64
#define SCB 98            // scan blocks: ceil(NN/1024)
#define TPB 64            // nodes per block in dense kernels
#define S2SCAP 320        // max cached nodes per graph in s2s

// ---------------- device scratch ----------------
__device__ float g_h1[NN * H1];
__device__ float g_s1[NN * H1];
__device__ float g_h2[NN * H2];
__device__ float g_e[NN];
__device__ int   g_cnt[NN];
__device__ int   g_off[NN + 1];
__device__ int   g_cur[NN];
__device__ int   g_csr[NE];
__device__ int   g_gs[NG + 1];
__device__ int   g_sagg[SCB];
__device__ int   g_sflag[SCB];

__device__ __forceinline__ float gelu_f(float x) {
    return 0.5f * x * (1.0f + erff(x * 0.70710678118654752f));
}
__device__ __forceinline__ float sigmoid_f(float x) {
    return 1.0f / (1.0f + expf(-x));
}

// ---------------- init ----------------
__global__ void __launch_bounds__(256) k_zero() {
    int i = blockIdx.x * blockDim.x + threadIdx.x;
    int T = gridDim.x * blockDim.x;
    for (int j = i; j < NN; j += T) { g_cnt[j] = 0; g_cur[j] = 0; }
    if (i < SCB) { g_sflag[i] = 0; g_sagg[i] = 0; }
    if (i == 0) g_off[NN] = NE;
}

// ---------------- nfc (64 nodes/block) + edge counting fold ----------------
__global__ void __launch_bounds__(256) k_nfc(const float* __restrict__ x,
                                             const float* __restrict__ W,
                                             const float* __restrict__ b,
                                             const int* __restrict__ ei) {
    extern __shared__ float sm[];
    float* wt = sm;                  // [64][128] transposed (32 KB)
    float* xs = sm + NF * H1;        // [64][64]  (16 KB)
    int tid = threadIdx.x;
    {
        int eb = blockIdx.x * 1024 + tid * 4;
#pragma unroll
        for (int i = 0; i < 4; i++)
            if (eb + i < NE) atomicAdd(&g_cnt[ei[NE + eb + i]], 1);
    }
    for (int i = tid; i < H1 * NF; i += 256) {
        int o = i >> 6, k = i & 63;
        wt[k * H1 + o] = W[i];
    }
    int warp = tid >> 5, lane = tid & 31;
    int nb = blockIdx.x * TPB;
#pragma unroll
    for (int t = 0; t < 8; t++) {
        int row = warp * 8 + t;
        int n = nb + row;
        if (n < NN) {
            float2 xv = *(const float2*)&x[n * NF + lane * 2];
            *(float2*)&xs[row * NF + lane * 2] = xv;
        }
    }
    __syncthreads();
    float4 bias = *(const float4*)&b[lane * 4];
    float4 acc[8];
#pragma unroll
    for (int t = 0; t < 8; t++) acc[t] = bias;
    const float* rp = &xs[warp * 8 * NF];
#pragma unroll 4
    for (int k = 0; k < NF; k++) {
        float4 w = *(const float4*)&wt[k * H1 + lane * 4];
#pragma unroll
        for (int t = 0; t < 8; t++) {
            float v = rp[t * NF + k];
            acc[t].x = fmaf(v, w.x, acc[t].x);
            acc[t].y = fmaf(v, w.y, acc[t].y);
            acc[t].z = fmaf(v, w.z, acc[t].z);
            acc[t].w = fmaf(v, w.w, acc[t].w);
        }
    }
#pragma unroll
    for (int t = 0; t < 8; t++) {
        int n = nb + warp * 8 + t;
        if (n < NN) {
            float4 a = acc[t];
            a.x = gelu_f(a.x); a.y = gelu_f(a.y);
            a.z = gelu_f(a.z); a.w = gelu_f(a.w);
            *(float4*)&g_h1[n * H1 + lane * 4] = a;
        }
    }
}

// ---------------- single-pass scan (decoupled lookback) + gstart fold ----------------
__global__ void __launch_bounds__(256) k_scan(const int* __restrict__ batch) {
    __shared__ int sm[256];
    __shared__ int addsh;
    int tid = threadIdx.x;
    int b = blockIdx.x;
    if (tid == 0) addsh = 0;
    int idx = b * 1024 + tid * 4;
    int v0 = 0, v1 = 0, v2 = 0, v3 = 0;
    if (idx     < NN) v0 = g_cnt[idx];
    if (idx + 1 < NN) v1 = g_cnt[idx + 1];
    if (idx + 2 < NN) v2 = g_cnt[idx + 2];
    if (idx + 3 < NN) v3 = g_cnt[idx + 3];
    int t = v0 + v1 + v2 + v3;
    sm[tid] = t;
    __syncthreads();
    for (int off = 1; off < 256; off <<= 1) {
        int u = (tid >= off) ? sm[tid - off] : 0;
        __syncthreads();
        sm[tid] += u;
        __syncthreads();
    }
    if (tid == 0) {
        g_sagg[b] = sm[255];
        __threadfence();
        atomicExch(&g_sflag[b], 1);
    }
    int excl = sm[tid] - t;
    int myadd = 0;
    for (int i = tid; i < b; i += 256) {
        while (((volatile int*)g_sflag)[i] == 0) { }
        myadd += ((volatile int*)g_sagg)[i];
    }
#pragma unroll
    for (int off = 16; off; off >>= 1) myadd += __shfl_xor_sync(0xFFFFFFFFu, myadd, off);
    if ((tid & 31) == 0 && myadd) atomicAdd(&addsh, myadd);
    __syncthreads();
    int add = addsh;
    if (idx     < NN) g_off[idx]     = excl + add;
    if (idx + 1 < NN) g_off[idx + 1] = excl + add + v0;
    if (idx + 2 < NN) g_off[idx + 2] = excl + add + v0 + v1;
    if (idx + 3 < NN) g_off[idx + 3] = excl + add + v0 + v1 + v2;
#pragma unroll
    for (int i = 0; i < 4; i++) {
        int n = idx + i;
        if (n < NN) {
            int bb = batch[n];
            int bp = (n == 0) ? -1 : batch[n - 1];
            for (int g = bp + 1; g <= bb; g++) g_gs[g] = n;
            if (n == NN - 1)
                for (int g = bb + 1; g <= NG; g++) g_gs[g] = NN;
        }
    }
}

// ---------------- gemm1t: g_s1 = g_h1 @ W1.T (no bias/act) + scatter fold ----------------
__global__ void __launch_bounds__(256) k_gemm1t(const float* __restrict__ W,
                                                const int* __restrict__ ei) {
    extern __shared__ float sm[];
    float* wt = sm;                  // [128][128] transposed (64 KB)
    float* as = sm + H1 * H1;        // [64][128] (32 KB)
    int tid = threadIdx.x;
    // scatter fold: this block's 1024 edges (CSR ready at next kernel boundary)
    {
        int eb = blockIdx.x * 1024 + tid * 4;
#pragma unroll
        for (int i = 0; i < 4; i++) {
            int e = eb + i;
            if (e < NE) {
                int s = ei[e];
                int d = ei[NE + e];
                int pos = atomicAdd(&g_cur[d], 1);
                g_csr[g_off[d] + pos] = s;
            }
        }
    }
    for (int i = tid; i < H1 * H1; i += 256) {
        int o = i >> 7, k = i & 127;
        wt[k * H1 + o] = W[i];
    }
    int nb = blockIdx.x * TPB;
    for (int i = tid; i < TPB * H1 / 4; i += 256) {
        int row = (i * 4) >> 7;
        int k   = (i * 4) & 127;
        int n = nb + row;
        float4 v = (n < NN) ? *(const float4*)&g_h1[n * H1 + k]
                            : make_float4(0.f, 0.f, 0.f, 0.f);
        *(float4*)&as[row * H1 + k] = v;
    }
    __syncthreads();
    int warp = tid >> 5, lane = tid & 31;
    float4 acc[8];
#pragma unroll
    for (int t = 0; t < 8; t++) acc[t] = make_float4(0.f, 0.f, 0.f, 0.f);
    const float* rp = &as[warp * 8 * H1];
#pragma unroll 4
    for (int k = 0; k < H1; k++) {
        float4 w = *(const float4*)&wt[k * H1 + lane * 4];
#pragma unroll
        for (int t = 0; t < 8; t++) {
            float v = rp[t * H1 + k];
            acc[t].x = fmaf(v, w.x, acc[t].x);
            acc[t].y = fmaf(v, w.y, acc[t].y);
            acc[t].z = fmaf(v, w.z, acc[t].z);
            acc[t].w = fmaf(v, w.w, acc[t].w);
        }
    }
#pragma unroll
    for (int t = 0; t < 8; t++) {
        int n = nb + warp * 8 + t;
        if (n < NN)
            *(float4*)&g_s1[n * H1 + lane * 4] = acc[t];
    }
}

// ---------------- gatherB: agg z1 (g_s1) -> +b1, gelu -> g_h1 ----------------
__global__ void __launch_bounds__(256) k_gatherB(const float* __restrict__ b1) {
    int n = (blockIdx.x * 256 + threadIdx.x) >> 5;
    int lane = threadIdx.x & 31;
    if (n >= NN) return;
    const float* src = g_s1;
    float4 a = *(const float4*)&src[n * H1 + lane * 4];
    int e0 = g_off[n], e1 = g_off[n + 1];
    int j = e0;
    for (; j + 7 < e1; j += 8) {
        int s0 = g_csr[j],     s1 = g_csr[j + 1], s2 = g_csr[j + 2], s3 = g_csr[j + 3];
        int s4 = g_csr[j + 4], s5 = g_csr[j + 5], s6 = g_csr[j + 6], s7 = g_csr[j + 7];
        float4 v0 = *(const float4*)&src[s0 * H1 + lane * 4];
        float4 v1 = *(const float4*)&src[s1 * H1 + lane * 4];
        float4 v2 = *(const float4*)&src[s2 * H1 + lane * 4];
        float4 v3 = *(const float4*)&src[s3 * H1 + lane * 4];
        float4 v4 = *(const float4*)&src[s4 * H1 + lane * 4];
        float4 v5 = *(const float4*)&src[s5 * H1 + lane * 4];
        float4 v6 = *(const float4*)&src[s6 * H1 + lane * 4];
        float4 v7 = *(const float4*)&src[s7 * H1 + lane * 4];
        a.x += ((v0.x + v1.x) + (v2.x + v3.x)) + ((v4.x + v5.x) + (v6.x + v7.x));
        a.y += ((v0.y + v1.y) + (v2.y + v3.y)) + ((v4.y + v5.y) + (v6.y + v7.y));
        a.z += ((v0.z + v1.z) + (v2.z + v3.z)) + ((v4.z + v5.z) + (v6.z + v7.z));
        a.w += ((v0.w + v1.w) + (v2.w + v3.w)) + ((v4.w + v5.w) + (v6.w + v7.w));
    }
    if (j + 3 < e1) {
        int s0 = g_csr[j], s1 = g_csr[j + 1], s2 = g_csr[j + 2], s3 = g_csr[j + 3];
        float4 v0 = *(const float4*)&src[s0 * H1 + lane * 4];
        float4 v1 = *(const float4*)&src[s1 * H1 + lane * 4];
        float4 v2 = *(const float4*)&src[s2 * H1 + lane * 4];
        float4 v3 = *(const float4*)&src[s3 * H1 + lane * 4];
        a.x += (v0.x + v1.x) + (v2.x + v3.x);
        a.y += (v0.y + v1.y) + (v2.y + v3.y);
        a.z += (v0.z + v1.z) + (v2.z + v3.z);
        a.w += (v0.w + v1.w) + (v2.w + v3.w);
        j += 4;
    }
    for (; j < e1; j++) {
        int s0 = g_csr[j];
        float4 v0 = *(const float4*)&src[s0 * H1 + lane * 4];
        a.x += v0.x; a.y += v0.y; a.z += v0.z; a.w += v0.w;
    }
    float4 bb = *(const float4*)&b1[lane * 4];
    a.x = gelu_f(a.x + bb.x); a.y = gelu_f(a.y + bb.y);
    a.z = gelu_f(a.z + bb.z); a.w = gelu_f(a.w + bb.w);
    *(float4*)&g_h1[n * H1 + lane * 4] = a;
}

// ---------------- gather: g_h1 -> g_s1 (plain agg) ----------------
__global__ void __launch_bounds__(256) k_gather() {
    int n = (blockIdx.x * 256 + threadIdx.x) >> 5;
    int lane = threadIdx.x & 31;
    if (n >= NN) return;
    const float* src = g_h1;
    float4 a = *(const float4*)&src[n * H1 + lane * 4];
    int e0 = g_off[n], e1 = g_off[n + 1];
    int j = e0;
    for (; j + 7 < e1; j += 8) {
        int s0 = g_csr[j],     s1 = g_csr[j + 1], s2 = g_csr[j + 2], s3 = g_csr[j + 3];
        int s4 = g_csr[j + 4], s5 = g_csr[j + 5], s6 = g_csr[j + 6], s7 = g_csr[j + 7];
        float4 v0 = *(const float4*)&src[s0 * H1 + lane * 4];
        float4 v1 = *(const float4*)&src[s1 * H1 + lane * 4];
        float4 v2 = *(const float4*)&src[s2 * H1 + lane * 4];
        float4 v3 = *(const float4*)&src[s3 * H1 + lane * 4];
        float4 v4 = *(const float4*)&src[s4 * H1 + lane * 4];
        float4 v5 = *(const float4*)&src[s5 * H1 + lane * 4];
        float4 v6 = *(const float4*)&src[s6 * H1 + lane * 4];
        float4 v7 = *(const float4*)&src[s7 * H1 + lane * 4];
        a.x += ((v0.x + v1.x) + (v2.x + v3.x)) + ((v4.x + v5.x) + (v6.x + v7.x));
        a.y += ((v0.y + v1.y) + (v2.y + v3.y)) + ((v4.y + v5.y) + (v6.y + v7.y));
        a.z += ((v0.z + v1.z) + (v2.z + v3.z)) + ((v4.z + v5.z) + (v6.z + v7.z));
        a.w += ((v0.w + v1.w) + (v2.w + v3.w)) + ((v4.w + v5.w) + (v6.w + v7.w));
    }
    if (j + 3 < e1) {
        int s0 = g_csr[j], s1 = g_csr[j + 1], s2 = g_csr[j + 2], s3 = g_csr[j + 3];
        float4 v0 = *(const float4*)&src[s0 * H1 + lane * 4];
        float4 v1 = *(const float4*)&src[s1 * H1 + lane * 4];
        float4 v2 = *(const float4*)&src[s2 * H1 + lane * 4];
        float4 v3 = *(const float4*)&src[s3 * H1 + lane * 4];
        a.x += (v0.x + v1.x) + (v2.x + v3.x);
        a.y += (v0.y + v1.y) + (v2.y + v3.y);
        a.z += (v0.z + v1.z) + (v2.z + v3.z);
        a.w += (v0.w + v1.w) + (v2.w + v3.w);
        j += 4;
    }
    for (; j < e1; j++) {
        int s0 = g_csr[j];
        float4 v0 = *(const float4*)&src[s0 * H1 + lane * 4];
        a.x += v0.x; a.y += v0.y; a.z += v0.z; a.w += v0.w;
    }
    *(float4*)&g_s1[n * H1 + lane * 4] = a;
}

// ---------------- gemm2: g_h2 = normalize(gelu(g_s1 @ W.T + b)) ----------------
__global__ void __launch_bounds__(256) k_gemm2(const float* __restrict__ W,
                                               const float* __restrict__ b,
                                               float* __restrict__ out_h) {
    extern __shared__ float sm[];
    float* wt = sm;                  // [128][64] transposed (32 KB)
    float* as = sm + H1 * H2;        // [64][128] (32 KB)
    int tid = threadIdx.x;
    for (int i = tid; i < H2 * H1; i += 256) {
        int o = i >> 7, k = i & 127;
        wt[k * H2 + o] = W[i];
    }
    int nb = blockIdx.x * TPB;
    for (int i = tid; i < TPB * H1 / 4; i += 256) {
        int row = (i * 4) >> 7;
        int k   = (i * 4) & 127;
        int n = nb + row;
        float4 v = (n < NN) ? *(const float4*)&g_s1[n * H1 + k]
                            : make_float4(0.f, 0.f, 0.f, 0.f);
        *(float4*)&as[row * H1 + k] = v;
    }
    __syncthreads();
    int warp = tid >> 5, lane = tid & 31;
    float2 bias = *(const float2*)&b[lane * 2];
    float2 acc[8];
#pragma unroll
    for (int t = 0; t < 8; t++) acc[t] = bias;
    const float* rp = &as[warp * 8 * H1];
#pragma unroll 4
    for (int k = 0; k < H1; k++) {
        float2 w = *(const float2*)&wt[k * H2 + lane * 2];
#pragma unroll
        for (int t = 0; t < 8; t++) {
            float v = rp[t * H1 + k];
            acc[t].x = fmaf(v, w.x, acc[t].x);
            acc[t].y = fmaf(v, w.y, acc[t].y);
        }
    }
#pragma unroll
    for (int t = 0; t < 8; t++) {
        int n = nb + warp * 8 + t;
        if (n < NN) {
            float2 a = acc[t];
            a.x = gelu_f(a.x);
            a.y = gelu_f(a.y);
            float ssq = a.x * a.x + a.y * a.y;
#pragma unroll
            for (int off = 16; off; off >>= 1) ssq += __shfl_xor_sync(0xFFFFFFFFu, ssq, off);
            float inv = 1.0f / fmaxf(sqrtf(ssq), 1e-12f);
            a.x *= inv; a.y *= inv;
            *(float2*)&g_h2[n * H2 + lane * 2] = a;
            if (out_h) *(float2*)&out_h[n * H2 + lane * 2] = a;
        }
    }
}

// ---------------- fused Set2Set + final MLP, graph h2 cached in smem ----------------
__global__ void __launch_bounds__(256) k_s2s(
        const float* __restrict__ Wih0, const float* __restrict__ Whh0,
        const float* __restrict__ bih0, const float* __restrict__ bhh0,
        const float* __restrict__ Wih1, const float* __restrict__ Whh1,
        const float* __restrict__ bih1, const float* __restrict__ bhh1,
        const float* __restrict__ fc1W, const float* __restrict__ fc1b,
        const float* __restrict__ fc2W, const float* __restrict__ fc2b,
        float* __restrict__ z) {
    extern __shared__ float dyn[];
    float* cache = dyn;                 // [S2SCAP][H2]
    float* esm   = dyn + S2SCAP * H2;   // [S2SCAP]
    __shared__ float h0[H2], c0[H2], h1[H2], c1[H2], qs[2 * H2];
    __shared__ float gb[4 * H2], red[8], rbuf[8 * H2];
    __shared__ float smax, ssum;
    int g = blockIdx.x;
    int tid = threadIdx.x, warp = tid >> 5, lane = tid & 31;
    int gs = g_gs[g], ge = g_gs[g + 1];
    int nv = ge - gs;
    const float* hp;
    float* ep;
    if (nv <= S2SCAP) {
        const float4* s4 = (const float4*)&g_h2[gs * H2];
        float4* d4 = (float4*)cache;
        int tot = nv * (H2 / 4);
        for (int i = tid; i < tot; i += 256) d4[i] = s4[i];
        hp = cache; ep = esm;
    } else {
        hp = &g_h2[gs * H2]; ep = &g_e[gs];
    }
    if (tid < H2) { h0[tid] = 0.0f; c0[tid] = 0.0f; h1[tid] = 0.0f; c1[tid] = 0.0f; }
    if (tid < 2 * H2) qs[tid] = 0.0f;
    __syncthreads();

    for (int step = 0; step < 4; step++) {
        for (int r = warp; r < 4 * H2; r += 8) {
            const float* wi = &Wih0[r * 2 * H2];
            float p = wi[lane] * qs[lane] + wi[lane + 32] * qs[lane + 32]
                    + wi[lane + 64] * qs[lane + 64] + wi[lane + 96] * qs[lane + 96];
            const float* wh = &Whh0[r * H2];
            p += wh[lane] * h0[lane] + wh[lane + 32] * h0[lane + 32];
#pragma unroll
            for (int off = 16; off; off >>= 1) p += __shfl_xor_sync(0xFFFFFFFFu, p, off);
            if (lane == 0) gb[r] = p + bih0[r] + bhh0[r];
        }
        __syncthreads();
        if (tid < H2) {
            float i = sigmoid_f(gb[tid]);
            float f = sigmoid_f(gb[H2 + tid]);
            float gg = tanhf(gb[2 * H2 + tid]);
            float o = sigmoid_f(gb[3 * H2 + tid]);
            float c = f * c0[tid] + i * gg;
            c0[tid] = c;
            h0[tid] = o * tanhf(c);
        }
        __syncthreads();
        for (int r = warp; r < 4 * H2; r += 8) {
            const float* wi = &Wih1[r * H2];
            float p = wi[lane] * h0[lane] + wi[lane + 32] * h0[lane + 32];
            const float* wh = &Whh1[r * H2];
            p += wh[lane] * h1[lane] + wh[lane + 32] * h1[lane + 32];
#pragma unroll
            for (int off = 16; off; off >>= 1) p += __shfl_xor_sync(0xFFFFFFFFu, p, off);
            if (lane == 0) gb[r] = p + bih1[r] + bhh1[r];
        }
        __syncthreads();
        if (tid < H2) {
            float i = sigmoid_f(gb[tid]);
            float f = sigmoid_f(gb[H2 + tid]);
            float gg = tanhf(gb[2 * H2 + tid]);
            float o = sigmoid_f(gb[3 * H2 + tid]);
            float c = f * c1[tid] + i * gg;
            c1[tid] = c;
            float h = o * tanhf(c);
            h1[tid] = h;
            qs[tid] = h;
        }
        __syncthreads();
        float wmax = -3.4e38f;
        for (int li = warp; li < nv; li += 8) {
            float2 hv = *(const float2*)&hp[li * H2 + lane * 2];
            float e = hv.x * qs[lane * 2] + hv.y * qs[lane * 2 + 1];
#pragma unroll
            for (int off = 16; off; off >>= 1) e += __shfl_xor_sync(0xFFFFFFFFu, e, off);
            if (lane == 0) ep[li] = e;
            wmax = fmaxf(wmax, e);
        }
        if (lane == 0) red[warp] = wmax;
        __syncthreads();
        if (tid == 0) {
            float m = red[0];
            for (int w = 1; w < 8; w++) m = fmaxf(m, red[w]);
            smax = m;
        }
        __syncthreads();
        float m = smax;
        float ps = 0.0f;
        for (int li = tid; li < nv; li += 256) {
            float ex = expf(ep[li] - m);
            ep[li] = ex;
            ps += ex;
        }
#pragma unroll
        for (int off = 16; off; off >>= 1) ps += __shfl_xor_sync(0xFFFFFFFFu, ps, off);
        if (lane == 0) red[warp] = ps;
        __syncthreads();
        if (tid == 0) {
            float s = 0.0f;
            for (int w = 0; w < 8; w++) s += red[w];
            ssum = s;
        }
        __syncthreads();
        float inv = 1.0f / (ssum + 1e-16f);
        float rx = 0.0f, ry = 0.0f;
        for (int li = warp; li < nv; li += 8) {
            float a = ep[li] * inv;
            float2 hv = *(const float2*)&hp[li * H2 + lane * 2];
            rx = fmaf(a, hv.x, rx);
            ry = fmaf(a, hv.y, ry);
        }
        rbuf[warp * H2 + lane * 2]     = rx;
        rbuf[warp * H2 + lane * 2 + 1] = ry;
        __syncthreads();
        if (tid < H2) {
            float r = 0.0f;
            for (int w = 0; w < 8; w++) r += rbuf[w * H2 + tid];
            qs[H2 + tid] = r;
        }
        __syncthreads();
    }

    for (int r = warp; r < 32; r += 8) {
        const float* wr = &fc1W[r * 2 * H2];
        float p = wr[lane] * qs[lane] + wr[lane + 32] * qs[lane + 32]
                + wr[lane + 64] * qs[lane + 64] + wr[lane + 96] * qs[lane + 96];
#pragma unroll
        for (int off = 16; off; off >>= 1) p += __shfl_xor_sync(0xFFFFFFFFu, p, off);
        if (lane == 0) gb[r] = gelu_f(p + fc1b[r]);
    }
    __syncthreads();
    if (warp == 0) {
        float v = gb[lane] * fc2W[lane];
#pragma unroll
        for (int off = 16; off; off >>= 1) v += __shfl_xor_sync(0xFFFFFFFFu, v, off);
        if (lane == 0) z[g] = v + fc2b[0];
    }
}

// ---------------- host ----------------
extern "C" void kernel_launch(void* const* d_in, const int* in_sizes, int n_in,
                              void* d_out, int out_size) {
    const float* x     = (const float*)d_in[0];
    const int*   ei    = (const int*)d_in[1];
    const int*   batch = (const int*)d_in[2];
    const float* nfcW  = (const float*)d_in[3];
    const float* nfcb  = (const float*)d_in[4];
    const float* gc1W  = (const float*)d_in[5];
    const float* gc1b  = (const float*)d_in[6];
    const float* gc2W  = (const float*)d_in[7];
    const float* gc2b  = (const float*)d_in[8];
    const float* l0Wih = (const float*)d_in[9];
    const float* l0Whh = (const float*)d_in[10];
    const float* l0bih = (const float*)d_in[11];
    const float* l0bhh = (const float*)d_in[12];
    const float* l1Wih = (const float*)d_in[13];
    const float* l1Whh = (const float*)d_in[14];
    const float* l1bih = (const float*)d_in[15];
    const float* l1bhh = (const float*)d_in[16];
    const float* fc1W  = (const float*)d_in[17];
    const float* fc1b  = (const float*)d_in[18];
    const float* fc2W  = (const float*)d_in[19];
    const float* fc2b  = (const float*)d_in[20];

    float* out = (float*)d_out;
    float* out_h = (out_size >= NG + NN * H2) ? (out + NG) : nullptr;

    int nblk = (NN + TPB - 1) / TPB;                      // 1563
    int gblk = (NN * 32 + 255) / 256;                     // 12500
    size_t sm_nfc   = (size_t)(NF * H1 + TPB * NF) * 4;   // 48 KB
    size_t sm_gemm1 = (size_t)(H1 * H1 + TPB * H1) * 4;   // 96 KB
    size_t sm_gemm2 = (size_t)(H1 * H2 + TPB * H1) * 4;   // 64 KB
    size_t sm_s2s   = (size_t)(S2SCAP * H2 + S2SCAP) * 4; // 83.2 KB
    cudaFuncSetAttribute(k_nfc,    cudaFuncAttributeMaxDynamicSharedMemorySize, (int)sm_nfc);
    cudaFuncSetAttribute(k_gemm1t, cudaFuncAttributeMaxDynamicSharedMemorySize, (int)sm_gemm1);
    cudaFuncSetAttribute(k_gemm2,  cudaFuncAttributeMaxDynamicSharedMemorySize, (int)sm_gemm2);
    cudaFuncSetAttribute(k_s2s,    cudaFuncAttributeMaxDynamicSharedMemorySize, (int)sm_s2s);

    k_zero<<<128, 256>>>();
    k_nfc<<<nblk, 256, sm_nfc>>>(x, nfcW, nfcb, ei);
    k_scan<<<SCB, 256>>>(batch);
    k_gemm1t<<<nblk, 256, sm_gemm1>>>(gc1W, ei);      // scatter folded in
    k_gatherB<<<gblk, 256>>>(gc1b);                   // agg z1, +b1, gelu -> g_h1
    k_gather<<<gblk, 256>>>();                        // agg h_mid -> g_s1
    k_gemm2<<<nblk, 256, sm_gemm2>>>(gc2W, gc2b, out_h);
    k_s2s<<<NG, 256, sm_s2s>>>(l0Wih, l0Whh, l0bih, l0bhh,
                               l1Wih, l1Whh, l1bih, l1bhh,
                               fc1W, fc1b, fc2W, fc2b, out);
}